// round 12
// baseline (speedup 1.0000x reference)
#include <cuda_runtime.h>
#include <cuda_fp16.h>
#include <cstdint>

// RelativeAttention B=2,H=16,L=2048,D=64 fp32.
// fp16 balanced split: S = qH*kH + qL*kH + qH*kL (exact to ~2^-22);
// PV = p_fp16 * v_fp16. 32 MMAs/tile/warp. cp.async pre-split K (hi/lo) + V.

#define LSEQ   2048
#define DH     64
#define NHEAD  32
#define BM     128
#define BN     64
#define NT     (LSEQ / BN)
#define NTHR   256
#define MAXREL 8
#define LOG2E  1.4426950408889634f
#define NELEM  (NHEAD * LSEQ * DH)

#define PITCH  144
#define BUFHALF 27648                 // 3 arrays * 64*144
#define OFF_BL  0
#define OFF_BUF 128
#define KHIB(b) (OFF_BUF + (b) * BUFHALF + 0)
#define KLOB(b) (OFF_BUF + (b) * BUFHALF + 9216)
#define VHIB(b) (OFF_BUF + (b) * BUFHALF + 18432)
#define SMEM_TOTAL (128 + 2 * BUFHALF)   // 55424 B/CTA -> 110.8 KB for 2 CTAs

__device__ __half gKV[3][NELEM];   // [0]=K_hi [1]=K_lo [2]=V

// ---------------- helpers ----------------
__device__ __forceinline__ uint32_t s2u(const void* p) {
    uint32_t a;
    asm("{ .reg .u64 t; cvta.to.shared.u64 t, %1; cvt.u32.u64 %0, t; }" : "=r"(a) : "l"(p));
    return a;
}
__device__ __forceinline__ uint32_t cvt2h(float lo, float hi) {   // f16x2 {lo|hi}
    __half2 t = __floats2half2_rn(lo, hi);
    return *reinterpret_cast<uint32_t*>(&t);
}
__device__ __forceinline__ void mma16816(float* c, const uint32_t* a, const uint32_t* b) {
    asm volatile(
        "mma.sync.aligned.m16n8k16.row.col.f32.f16.f16.f32 "
        "{%0,%1,%2,%3}, {%4,%5,%6,%7}, {%8,%9}, {%0,%1,%2,%3};"
        : "+f"(c[0]), "+f"(c[1]), "+f"(c[2]), "+f"(c[3])
        : "r"(a[0]), "r"(a[1]), "r"(a[2]), "r"(a[3]), "r"(b[0]), "r"(b[1]));
}
__device__ __forceinline__ void ldsm4(uint32_t* r, uint32_t addr) {
    asm volatile("ldmatrix.sync.aligned.m8n8.x4.shared.b16 {%0,%1,%2,%3}, [%4];"
                 : "=r"(r[0]), "=r"(r[1]), "=r"(r[2]), "=r"(r[3]) : "r"(addr));
}
__device__ __forceinline__ void ldsm4t(uint32_t* r, uint32_t addr) {
    asm volatile("ldmatrix.sync.aligned.m8n8.x4.trans.shared.b16 {%0,%1,%2,%3}, [%4];"
                 : "=r"(r[0]), "=r"(r[1]), "=r"(r[2]), "=r"(r[3]) : "r"(addr));
}
__device__ __forceinline__ float exp2_fast(float x) {   // arg in [-32,-3]
    float t = x + 12582912.0f;
    float n = t - 12582912.0f;
    float f = x - n;
    float p = 0.0013333558f;
    p = fmaf(p, f, 0.0096181291f);
    p = fmaf(p, f, 0.0555041090f);
    p = fmaf(p, f, 0.2402265069f);
    p = fmaf(p, f, 0.6931471806f);
    p = fmaf(p, f, 1.0f);
    return __int_as_float(__float_as_int(p) + (__float_as_int(t) << 23));
}
// split float4 -> fp16 hi pair + fp16 residual pair
__device__ __forceinline__ void split4h(float4 v, uint32_t& h0, uint32_t& h1,
                                        uint32_t& l0, uint32_t& l1) {
    __half2 a = __floats2half2_rn(v.x, v.y);
    __half2 b = __floats2half2_rn(v.z, v.w);
    float rx = v.x - __half2float(__low2half(a));
    float ry = v.y - __half2float(__high2half(a));
    float rz = v.z - __half2float(__low2half(b));
    float rw = v.w - __half2float(__high2half(b));
    __half2 c = __floats2half2_rn(rx, ry);
    __half2 d = __floats2half2_rn(rz, rw);
    h0 = *reinterpret_cast<uint32_t*>(&a);
    h1 = *reinterpret_cast<uint32_t*>(&b);
    l0 = *reinterpret_cast<uint32_t*>(&c);
    l1 = *reinterpret_cast<uint32_t*>(&d);
}
#define CPASYNC16(dst, src) \
    asm volatile("cp.async.cg.shared.global [%0], [%1], 16;" :: "r"(dst), "l"(src))
#define CP_COMMIT() asm volatile("cp.async.commit_group;" ::: "memory")
#define CP_WAIT0()  asm volatile("cp.async.wait_group 0;" ::: "memory")

// ---------------- pre-kernel: K -> fp16 hi/lo, V -> fp16 ----------------
__global__ void __launch_bounds__(256)
convert_kv(const float* __restrict__ k, const float* __restrict__ v) {
    const size_t i = ((size_t)blockIdx.x * 256 + threadIdx.x) * 4;
    float4 kx = *(const float4*)(k + i);
    float4 vx = *(const float4*)(v + i);
    uint32_t h0, h1, l0, l1;
    split4h(kx, h0, h1, l0, l1);
    *(uint2*)(&gKV[0][i]) = make_uint2(h0, h1);
    *(uint2*)(&gKV[1][i]) = make_uint2(l0, l1);
    *(uint2*)(&gKV[2][i]) = make_uint2(cvt2h(vx.x, vx.y), cvt2h(vx.z, vx.w));
}

// ---------------- main kernel ----------------
__global__ void __launch_bounds__(NTHR, 2)
relattn_mma(const float* __restrict__ q, const float* __restrict__ bias,
            float* __restrict__ out) {
    extern __shared__ char smem[];
    const uint32_t sb = s2u(smem);
    float* bl = (float*)(smem + OFF_BL);

    const int tid  = threadIdx.x;
    const int wid  = tid >> 5;
    const int lane = tid & 31;
    const int head = blockIdx.y;
    const int q0   = blockIdx.x * BM;

    const float* qh = q + (size_t)head * LSEQ * DH;
    float*       oh = out + (size_t)head * LSEQ * DH;
    const size_t hb = (size_t)head * LSEQ * DH;

    const int crow = tid >> 2;
    const int cg   = (tid & 3) * 2;
    const uint32_t cdst = sb + (uint32_t)(crow * PITCH + cg * 16);

#define ISSUE_KV(n0_, buf_) do {                                              \
        const __half* s_ = &gKV[0][hb + (size_t)((n0_) + crow) * DH + cg * 8]; \
        CPASYNC16(cdst + KHIB(buf_),      s_);                                \
        CPASYNC16(cdst + KHIB(buf_) + 16, s_ + 8);                            \
        CPASYNC16(cdst + KLOB(buf_),      s_ + NELEM);                        \
        CPASYNC16(cdst + KLOB(buf_) + 16, s_ + NELEM + 8);                    \
        CPASYNC16(cdst + VHIB(buf_),      s_ + 2 * NELEM);                    \
        CPASYNC16(cdst + VHIB(buf_) + 16, s_ + 2 * NELEM + 8);                \
        CP_COMMIT();                                                          \
    } while (0)

    ISSUE_KV(0, 0);

    if (tid < 2 * MAXREL + 1)
        bl[tid] = (bias[tid] - 12.0f) * LOG2E;

    // ---- persistent Q fragments: fp16 hi + residual lo (pre-scaled 1/8) ----
    const int row0 = q0 + wid * 16 + (lane >> 2);
    const int ccol = (lane & 3) * 2;
    uint32_t qHf[4][4], qLf[4][4];
#pragma unroll
    for (int s = 0; s < 4; ++s) {
        const int c = s * 16 + ccol;
        float2 x0 = *(const float2*)&qh[(size_t)row0 * DH + c];
        float2 x1 = *(const float2*)&qh[(size_t)(row0 + 8) * DH + c];
        float2 x2 = *(const float2*)&qh[(size_t)row0 * DH + c + 8];
        float2 x3 = *(const float2*)&qh[(size_t)(row0 + 8) * DH + c + 8];
        float4 a = make_float4(x0.x * 0.125f, x0.y * 0.125f, x1.x * 0.125f, x1.y * 0.125f);
        float4 b = make_float4(x2.x * 0.125f, x2.y * 0.125f, x3.x * 0.125f, x3.y * 0.125f);
        split4h(a, qHf[s][0], qHf[s][1], qLf[s][0], qLf[s][1]);
        split4h(b, qHf[s][2], qHf[s][3], qLf[s][2], qLf[s][3]);
    }

    const uint32_t laneK = (uint32_t)(((lane & 7) + ((lane >> 4) & 1) * 8) * PITCH
                                      + ((lane >> 3) & 1) * 16);
    const uint32_t laneV = (uint32_t)(((lane & 7) + ((lane >> 3) & 1) * 8) * PITCH
                                      + ((lane >> 4) & 1) * 16);

    float oc[8][4];
#pragma unroll
    for (int i = 0; i < 8; ++i)
#pragma unroll
        for (int j = 0; j < 4; ++j) oc[i][j] = 0.0f;
    float rs0 = 0.0f, rs1 = 0.0f;
    const int relb = ccol - row0;

    for (int t = 0; t < NT; ++t) {
        const int n0 = t * BN;
        const int buf = t & 1;

        CP_WAIT0();
        __syncthreads();                       // tile t staged; t-1 consumed

        if (t + 1 < NT) ISSUE_KV(n0 + BN, buf ^ 1);

        const int mx = n0 + BN - 1 - q0;
        const int mn = n0 - (q0 + BM - 1);
        const bool generic = (mx > -MAXREL) && (mn < MAXREL);
        const float blc = (mx <= -MAXREL) ? bl[0] : bl[2 * MAXREL];

        // ---- per 16-col chunk: S-MMA (3-term) -> exp -> PV-MMA ----
#pragma unroll
        for (int np = 0; np < 4; ++np) {
            float se[4] = {0.f, 0.f, 0.f, 0.f};
            float so[4] = {0.f, 0.f, 0.f, 0.f};
#pragma unroll
            for (int s = 0; s < 4; ++s) {
                uint32_t kH[4], kL[4];
                uint32_t a = sb + (uint32_t)(np * 16 * PITCH + s * 32) + laneK;
                ldsm4(kH, a + KHIB(buf));
                ldsm4(kL, a + KLOB(buf));
                // S = qH*kH + qL*kH + qH*kL (qL*kL ~ 2^-24, dropped)
                mma16816(se, qHf[s], kH);
                mma16816(so, qHf[s], kH + 2);
                mma16816(se, qLf[s], kH);
                mma16816(so, qLf[s], kH + 2);
                mma16816(se, qHf[s], kL);
                mma16816(so, qHf[s], kL + 2);
            }

            // exp -> single-fp16 P a-fragment
            uint32_t pH[4];
#pragma unroll
            for (int h = 0; h < 2; ++h) {
                float* c = h ? so : se;
                float e0, e1, e2, e3;
                if (generic) {
                    const int r0i = relb + n0 + (2 * np + h) * 8;
                    const float b0 = bl[min(max(r0i,     -MAXREL), MAXREL) + MAXREL];
                    const float b1 = bl[min(max(r0i + 1, -MAXREL), MAXREL) + MAXREL];
                    const float b2 = bl[min(max(r0i - 8, -MAXREL), MAXREL) + MAXREL];
                    const float b3 = bl[min(max(r0i - 7, -MAXREL), MAXREL) + MAXREL];
                    e0 = exp2_fast(fmaf(c[0], LOG2E, b0));
                    e1 = exp2_fast(fmaf(c[1], LOG2E, b1));
                    e2 = exp2_fast(fmaf(c[2], LOG2E, b2));
                    e3 = exp2_fast(fmaf(c[3], LOG2E, b3));
                } else {
                    e0 = exp2_fast(fmaf(c[0], LOG2E, blc));
                    e1 = exp2_fast(fmaf(c[1], LOG2E, blc));
                    e2 = exp2_fast(fmaf(c[2], LOG2E, blc));
                    e3 = exp2_fast(fmaf(c[3], LOG2E, blc));
                }
                rs0 += e0 + e1;
                rs1 += e2 + e3;
                pH[2 * h]     = cvt2h(e0, e1);
                pH[2 * h + 1] = cvt2h(e2, e3);
            }

            // PV: oc += p * v (single-term V)
#pragma unroll
            for (int j = 0; j < 4; ++j) {
                uint32_t vH[4];
                ldsm4t(vH, sb + (uint32_t)(np * 16 * PITCH + j * 32) + laneV + VHIB(buf));
                mma16816(oc[2 * j],     pH, vH);
                mma16816(oc[2 * j + 1], pH, vH + 2);
            }
        }
    }

    // ---- epilogue ----
    rs0 += __shfl_xor_sync(0xffffffffu, rs0, 1);
    rs0 += __shfl_xor_sync(0xffffffffu, rs0, 2);
    rs1 += __shfl_xor_sync(0xffffffffu, rs1, 1);
    rs1 += __shfl_xor_sync(0xffffffffu, rs1, 2);
    const float inv0 = 1.0f / rs0;
    const float inv1 = 1.0f / rs1;

    float* d0 = oh + (size_t)row0 * DH + ccol;
    float* d1 = d0 + 8 * DH;
#pragma unroll
    for (int nt = 0; nt < 8; ++nt) {
        *(float2*)(d0 + nt * 8) = make_float2(oc[nt][0] * inv0, oc[nt][1] * inv0);
        *(float2*)(d1 + nt * 8) = make_float2(oc[nt][2] * inv1, oc[nt][3] * inv1);
    }
}

extern "C" void kernel_launch(void* const* d_in, const int* in_sizes, int n_in,
                              void* d_out, int out_size) {
    (void)in_sizes; (void)n_in; (void)out_size;
    const float* q    = (const float*)d_in[0];
    const float* k    = (const float*)d_in[1];
    const float* v    = (const float*)d_in[2];
    const float* bias = (const float*)d_in[3];
    float* out = (float*)d_out;

    convert_kv<<<NELEM / (256 * 4), 256>>>(k, v);

    cudaFuncSetAttribute(relattn_mma, cudaFuncAttributeMaxDynamicSharedMemorySize,
                         SMEM_TOTAL);
    dim3 grid(LSEQ / BM, NHEAD);
    relattn_mma<<<grid, NTHR, SMEM_TOTAL>>>(q, bias, out);
}

// round 13
// speedup vs baseline: 1.5066x; 1.5066x over previous
#include <cuda_runtime.h>
#include <cuda_fp16.h>
#include <cstdint>

// RelativeAttention B=2,H=16,L=2048,D=64 fp32.
// fp16 splits: S = q*(kH+kL) [16 MMAs], PV = (pH+pL)*v [16 MMAs].
// P split kills the dominant quantization error; R11's balanced chain shape.
// Pre-split K (hi/lo) + V (fp16) in gmem; cp.async; 8 warps M=16; 2 CTAs/SM.

#define LSEQ   2048
#define DH     64
#define NHEAD  32
#define BM     128
#define BN     64
#define NT     (LSEQ / BN)
#define NTHR   256
#define MAXREL 8
#define LOG2E  1.4426950408889634f
#define NELEM  (NHEAD * LSEQ * DH)

#define PITCH  144
#define BUFHALF 27648                 // 3 arrays * 64*144
#define OFF_BL  0
#define OFF_BUF 128
#define KHIB(b) (OFF_BUF + (b) * BUFHALF + 0)
#define KLOB(b) (OFF_BUF + (b) * BUFHALF + 9216)
#define VHIB(b) (OFF_BUF + (b) * BUFHALF + 18432)
#define SMEM_TOTAL (128 + 2 * BUFHALF)   // 55424 B/CTA

__device__ __half gKV[3][NELEM];   // [0]=K_hi [1]=K_lo [2]=V

// ---------------- helpers ----------------
__device__ __forceinline__ uint32_t s2u(const void* p) {
    uint32_t a;
    asm("{ .reg .u64 t; cvta.to.shared.u64 t, %1; cvt.u32.u64 %0, t; }" : "=r"(a) : "l"(p));
    return a;
}
__device__ __forceinline__ uint32_t cvt2h(float lo, float hi) {   // f16x2 {lo|hi}
    __half2 t = __floats2half2_rn(lo, hi);
    return *reinterpret_cast<uint32_t*>(&t);
}
__device__ __forceinline__ float h2lo(uint32_t p) {
    __half2 t = *reinterpret_cast<__half2*>(&p);
    return __half2float(__low2half(t));
}
__device__ __forceinline__ float h2hi(uint32_t p) {
    __half2 t = *reinterpret_cast<__half2*>(&p);
    return __half2float(__high2half(t));
}
__device__ __forceinline__ void mma16816(float* c, const uint32_t* a, const uint32_t* b) {
    asm volatile(
        "mma.sync.aligned.m16n8k16.row.col.f32.f16.f16.f32 "
        "{%0,%1,%2,%3}, {%4,%5,%6,%7}, {%8,%9}, {%0,%1,%2,%3};"
        : "+f"(c[0]), "+f"(c[1]), "+f"(c[2]), "+f"(c[3])
        : "r"(a[0]), "r"(a[1]), "r"(a[2]), "r"(a[3]), "r"(b[0]), "r"(b[1]));
}
__device__ __forceinline__ void ldsm4(uint32_t* r, uint32_t addr) {
    asm volatile("ldmatrix.sync.aligned.m8n8.x4.shared.b16 {%0,%1,%2,%3}, [%4];"
                 : "=r"(r[0]), "=r"(r[1]), "=r"(r[2]), "=r"(r[3]) : "r"(addr));
}
__device__ __forceinline__ void ldsm4t(uint32_t* r, uint32_t addr) {
    asm volatile("ldmatrix.sync.aligned.m8n8.x4.trans.shared.b16 {%0,%1,%2,%3}, [%4];"
                 : "=r"(r[0]), "=r"(r[1]), "=r"(r[2]), "=r"(r[3]) : "r"(addr));
}
__device__ __forceinline__ float exp2_fast(float x) {   // arg in [-32,-3]
    float t = x + 12582912.0f;
    float n = t - 12582912.0f;
    float f = x - n;
    float p = 0.0013333558f;
    p = fmaf(p, f, 0.0096181291f);
    p = fmaf(p, f, 0.0555041090f);
    p = fmaf(p, f, 0.2402265069f);
    p = fmaf(p, f, 0.6931471806f);
    p = fmaf(p, f, 1.0f);
    return __int_as_float(__float_as_int(p) + (__float_as_int(t) << 23));
}
// split float4 -> fp16 hi pair + fp16 residual pair
__device__ __forceinline__ void split4h(float4 v, uint32_t& h0, uint32_t& h1,
                                        uint32_t& l0, uint32_t& l1) {
    __half2 a = __floats2half2_rn(v.x, v.y);
    __half2 b = __floats2half2_rn(v.z, v.w);
    float rx = v.x - __half2float(__low2half(a));
    float ry = v.y - __half2float(__high2half(a));
    float rz = v.z - __half2float(__low2half(b));
    float rw = v.w - __half2float(__high2half(b));
    __half2 c = __floats2half2_rn(rx, ry);
    __half2 d = __floats2half2_rn(rz, rw);
    h0 = *reinterpret_cast<uint32_t*>(&a);
    h1 = *reinterpret_cast<uint32_t*>(&b);
    l0 = *reinterpret_cast<uint32_t*>(&c);
    l1 = *reinterpret_cast<uint32_t*>(&d);
}
#define CPASYNC16(dst, src) \
    asm volatile("cp.async.cg.shared.global [%0], [%1], 16;" :: "r"(dst), "l"(src))
#define CP_COMMIT() asm volatile("cp.async.commit_group;" ::: "memory")
#define CP_WAIT0()  asm volatile("cp.async.wait_group 0;" ::: "memory")

// ---------------- pre-kernel: K -> fp16 hi/lo, V -> fp16 ----------------
__global__ void __launch_bounds__(256)
convert_kv(const float* __restrict__ k, const float* __restrict__ v) {
    const size_t i = ((size_t)blockIdx.x * 256 + threadIdx.x) * 4;
    float4 kx = *(const float4*)(k + i);
    float4 vx = *(const float4*)(v + i);
    uint32_t h0, h1, l0, l1;
    split4h(kx, h0, h1, l0, l1);
    *(uint2*)(&gKV[0][i]) = make_uint2(h0, h1);
    *(uint2*)(&gKV[1][i]) = make_uint2(l0, l1);
    *(uint2*)(&gKV[2][i]) = make_uint2(cvt2h(vx.x, vx.y), cvt2h(vx.z, vx.w));
}

// ---------------- main kernel ----------------
__global__ void __launch_bounds__(NTHR, 2)
relattn_mma(const float* __restrict__ q, const float* __restrict__ bias,
            float* __restrict__ out) {
    extern __shared__ char smem[];
    const uint32_t sb = s2u(smem);
    float* bl = (float*)(smem + OFF_BL);

    const int tid  = threadIdx.x;
    const int wid  = tid >> 5;
    const int lane = tid & 31;
    const int head = blockIdx.y;
    const int q0   = blockIdx.x * BM;

    const float* qh = q + (size_t)head * LSEQ * DH;
    float*       oh = out + (size_t)head * LSEQ * DH;
    const size_t hb = (size_t)head * LSEQ * DH;

    const int crow = tid >> 2;
    const int cg   = (tid & 3) * 2;
    const uint32_t cdst = sb + (uint32_t)(crow * PITCH + cg * 16);

#define ISSUE_KV(n0_, buf_) do {                                              \
        const __half* s_ = &gKV[0][hb + (size_t)((n0_) + crow) * DH + cg * 8]; \
        CPASYNC16(cdst + KHIB(buf_),      s_);                                \
        CPASYNC16(cdst + KHIB(buf_) + 16, s_ + 8);                            \
        CPASYNC16(cdst + KLOB(buf_),      s_ + NELEM);                        \
        CPASYNC16(cdst + KLOB(buf_) + 16, s_ + NELEM + 8);                    \
        CPASYNC16(cdst + VHIB(buf_),      s_ + 2 * NELEM);                    \
        CPASYNC16(cdst + VHIB(buf_) + 16, s_ + 2 * NELEM + 8);                \
        CP_COMMIT();                                                          \
    } while (0)

    ISSUE_KV(0, 0);

    if (tid < 2 * MAXREL + 1)
        bl[tid] = (bias[tid] - 12.0f) * LOG2E;

    // ---- persistent Q fragments (single fp16, pre-scaled 1/8) ----
    const int row0 = q0 + wid * 16 + (lane >> 2);
    const int ccol = (lane & 3) * 2;
    uint32_t qf[4][4];
#pragma unroll
    for (int s = 0; s < 4; ++s) {
        const int c = s * 16 + ccol;
        float2 x0 = *(const float2*)&qh[(size_t)row0 * DH + c];
        float2 x1 = *(const float2*)&qh[(size_t)(row0 + 8) * DH + c];
        float2 x2 = *(const float2*)&qh[(size_t)row0 * DH + c + 8];
        float2 x3 = *(const float2*)&qh[(size_t)(row0 + 8) * DH + c + 8];
        qf[s][0] = cvt2h(x0.x * 0.125f, x0.y * 0.125f);
        qf[s][1] = cvt2h(x1.x * 0.125f, x1.y * 0.125f);
        qf[s][2] = cvt2h(x2.x * 0.125f, x2.y * 0.125f);
        qf[s][3] = cvt2h(x3.x * 0.125f, x3.y * 0.125f);
    }

    const uint32_t laneK = (uint32_t)(((lane & 7) + ((lane >> 4) & 1) * 8) * PITCH
                                      + ((lane >> 3) & 1) * 16);
    const uint32_t laneV = (uint32_t)(((lane & 7) + ((lane >> 3) & 1) * 8) * PITCH
                                      + ((lane >> 4) & 1) * 16);

    float oc[8][4];
#pragma unroll
    for (int i = 0; i < 8; ++i)
#pragma unroll
        for (int j = 0; j < 4; ++j) oc[i][j] = 0.0f;
    float rs0 = 0.0f, rs1 = 0.0f;
    const int relb = ccol - row0;

    for (int t = 0; t < NT; ++t) {
        const int n0 = t * BN;
        const int buf = t & 1;

        CP_WAIT0();
        __syncthreads();                       // tile t staged; t-1 consumed

        if (t + 1 < NT) ISSUE_KV(n0 + BN, buf ^ 1);

        const int mx = n0 + BN - 1 - q0;
        const int mn = n0 - (q0 + BM - 1);
        const bool generic = (mx > -MAXREL) && (mn < MAXREL);
        const float blc = (mx <= -MAXREL) ? bl[0] : bl[2 * MAXREL];

        // ---- per 16-col chunk: S-MMA -> exp -> split-P -> PV-MMA ----
#pragma unroll
        for (int np = 0; np < 4; ++np) {
            float se[4] = {0.f, 0.f, 0.f, 0.f};
            float so[4] = {0.f, 0.f, 0.f, 0.f};
#pragma unroll
            for (int s = 0; s < 4; ++s) {
                uint32_t kH[4], kL[4];
                uint32_t a = sb + (uint32_t)(np * 16 * PITCH + s * 32) + laneK;
                ldsm4(kH, a + KHIB(buf));
                ldsm4(kL, a + KLOB(buf));
                // S = q*(kH + kL); q-quant proven negligible
                mma16816(se, qf[s], kH);
                mma16816(so, qf[s], kH + 2);
                mma16816(se, qf[s], kL);
                mma16816(so, qf[s], kL + 2);
            }

            // exp -> P hi/lo a-fragments (P effectively exact)
            uint32_t pH[4], pL[4];
#pragma unroll
            for (int h = 0; h < 2; ++h) {
                float* c = h ? so : se;
                float e0, e1, e2, e3;
                if (generic) {
                    const int r0i = relb + n0 + (2 * np + h) * 8;
                    const float b0 = bl[min(max(r0i,     -MAXREL), MAXREL) + MAXREL];
                    const float b1 = bl[min(max(r0i + 1, -MAXREL), MAXREL) + MAXREL];
                    const float b2 = bl[min(max(r0i - 8, -MAXREL), MAXREL) + MAXREL];
                    const float b3 = bl[min(max(r0i - 7, -MAXREL), MAXREL) + MAXREL];
                    e0 = exp2_fast(fmaf(c[0], LOG2E, b0));
                    e1 = exp2_fast(fmaf(c[1], LOG2E, b1));
                    e2 = exp2_fast(fmaf(c[2], LOG2E, b2));
                    e3 = exp2_fast(fmaf(c[3], LOG2E, b3));
                } else {
                    e0 = exp2_fast(fmaf(c[0], LOG2E, blc));
                    e1 = exp2_fast(fmaf(c[1], LOG2E, blc));
                    e2 = exp2_fast(fmaf(c[2], LOG2E, blc));
                    e3 = exp2_fast(fmaf(c[3], LOG2E, blc));
                }
                rs0 += e0 + e1;
                rs1 += e2 + e3;
                uint32_t h01 = cvt2h(e0, e1), h23 = cvt2h(e2, e3);
                pH[2 * h]     = h01;
                pH[2 * h + 1] = h23;
                pL[2 * h]     = cvt2h(e0 - h2lo(h01), e1 - h2hi(h01));
                pL[2 * h + 1] = cvt2h(e2 - h2lo(h23), e3 - h2hi(h23));
            }

            // PV: oc += (pH + pL) * v
#pragma unroll
            for (int j = 0; j < 4; ++j) {
                uint32_t vH[4];
                ldsm4t(vH, sb + (uint32_t)(np * 16 * PITCH + j * 32) + laneV + VHIB(buf));
                mma16816(oc[2 * j],     pH, vH);
                mma16816(oc[2 * j + 1], pH, vH + 2);
                mma16816(oc[2 * j],     pL, vH);
                mma16816(oc[2 * j + 1], pL, vH + 2);
            }
        }
    }

    // ---- epilogue ----
    rs0 += __shfl_xor_sync(0xffffffffu, rs0, 1);
    rs0 += __shfl_xor_sync(0xffffffffu, rs0, 2);
    rs1 += __shfl_xor_sync(0xffffffffu, rs1, 1);
    rs1 += __shfl_xor_sync(0xffffffffu, rs1, 2);
    const float inv0 = 1.0f / rs0;
    const float inv1 = 1.0f / rs1;

    float* d0 = oh + (size_t)row0 * DH + ccol;
    float* d1 = d0 + 8 * DH;
#pragma unroll
    for (int nt = 0; nt < 8; ++nt) {
        *(float2*)(d0 + nt * 8) = make_float2(oc[nt][0] * inv0, oc[nt][1] * inv0);
        *(float2*)(d1 + nt * 8) = make_float2(oc[nt][2] * inv1, oc[nt][3] * inv1);
    }
}

extern "C" void kernel_launch(void* const* d_in, const int* in_sizes, int n_in,
                              void* d_out, int out_size) {
    (void)in_sizes; (void)n_in; (void)out_size;
    const float* q    = (const float*)d_in[0];
    const float* k    = (const float*)d_in[1];
    const float* v    = (const float*)d_in[2];
    const float* bias = (const float*)d_in[3];
    float* out = (float*)d_out;

    convert_kv<<<NELEM / (256 * 4), 256>>>(k, v);

    cudaFuncSetAttribute(relattn_mma, cudaFuncAttributeMaxDynamicSharedMemorySize,
                         SMEM_TOTAL);
    dim3 grid(LSEQ / BM, NHEAD);
    relattn_mma<<<grid, NTHR, SMEM_TOTAL>>>(q, bias, out);
}

// round 14
// speedup vs baseline: 1.5318x; 1.0167x over previous
#include <cuda_runtime.h>
#include <cuda_fp16.h>
#include <cstdint>

// RelativeAttention B=2,H=16,L=2048,D=64 fp32.
// R13 math (S = q*(kH+kL), PV = (pH+pL)*v, 32 MMAs/tile/warp) + split-K=4:
// 2048 work units kill wave-quantization tail; combine kernel normalizes.

#define LSEQ   2048
#define DH     64
#define NHEAD  32
#define BM     128
#define BN     64
#define NSPLIT 4
#define TPS    (LSEQ / BN / NSPLIT)   // 8 tiles per split
#define NTHR   256
#define MAXREL 8
#define LOG2E  1.4426950408889634f
#define NELEM  (NHEAD * LSEQ * DH)

#define PITCH  144
#define BUFHALF 27648                 // 3 arrays * 64*144
#define OFF_BL  0
#define OFF_BUF 128
#define KHIB(b) (OFF_BUF + (b) * BUFHALF + 0)
#define KLOB(b) (OFF_BUF + (b) * BUFHALF + 9216)
#define VHIB(b) (OFF_BUF + (b) * BUFHALF + 18432)
#define SMEM_TOTAL (128 + 2 * BUFHALF)   // 55424 B/CTA

__device__ __half gKV[3][NELEM];            // [0]=K_hi [1]=K_lo [2]=V
__device__ float  gO[NSPLIT * NELEM];       // unnormalized partial O (64 MB)
__device__ float  gRS[NSPLIT * NHEAD * LSEQ];  // partial rowsums (1 MB)

// ---------------- helpers ----------------
__device__ __forceinline__ uint32_t s2u(const void* p) {
    uint32_t a;
    asm("{ .reg .u64 t; cvta.to.shared.u64 t, %1; cvt.u32.u64 %0, t; }" : "=r"(a) : "l"(p));
    return a;
}
__device__ __forceinline__ uint32_t cvt2h(float lo, float hi) {
    __half2 t = __floats2half2_rn(lo, hi);
    return *reinterpret_cast<uint32_t*>(&t);
}
__device__ __forceinline__ float h2lo(uint32_t p) {
    __half2 t = *reinterpret_cast<__half2*>(&p);
    return __half2float(__low2half(t));
}
__device__ __forceinline__ float h2hi(uint32_t p) {
    __half2 t = *reinterpret_cast<__half2*>(&p);
    return __half2float(__high2half(t));
}
__device__ __forceinline__ void mma16816(float* c, const uint32_t* a, const uint32_t* b) {
    asm volatile(
        "mma.sync.aligned.m16n8k16.row.col.f32.f16.f16.f32 "
        "{%0,%1,%2,%3}, {%4,%5,%6,%7}, {%8,%9}, {%0,%1,%2,%3};"
        : "+f"(c[0]), "+f"(c[1]), "+f"(c[2]), "+f"(c[3])
        : "r"(a[0]), "r"(a[1]), "r"(a[2]), "r"(a[3]), "r"(b[0]), "r"(b[1]));
}
__device__ __forceinline__ void ldsm4(uint32_t* r, uint32_t addr) {
    asm volatile("ldmatrix.sync.aligned.m8n8.x4.shared.b16 {%0,%1,%2,%3}, [%4];"
                 : "=r"(r[0]), "=r"(r[1]), "=r"(r[2]), "=r"(r[3]) : "r"(addr));
}
__device__ __forceinline__ void ldsm4t(uint32_t* r, uint32_t addr) {
    asm volatile("ldmatrix.sync.aligned.m8n8.x4.trans.shared.b16 {%0,%1,%2,%3}, [%4];"
                 : "=r"(r[0]), "=r"(r[1]), "=r"(r[2]), "=r"(r[3]) : "r"(addr));
}
__device__ __forceinline__ float exp2_fast(float x) {   // arg in [-32,-3]
    float t = x + 12582912.0f;
    float n = t - 12582912.0f;
    float f = x - n;
    float p = 0.0013333558f;
    p = fmaf(p, f, 0.0096181291f);
    p = fmaf(p, f, 0.0555041090f);
    p = fmaf(p, f, 0.2402265069f);
    p = fmaf(p, f, 0.6931471806f);
    p = fmaf(p, f, 1.0f);
    return __int_as_float(__float_as_int(p) + (__float_as_int(t) << 23));
}
__device__ __forceinline__ void split4h(float4 v, uint32_t& h0, uint32_t& h1,
                                        uint32_t& l0, uint32_t& l1) {
    __half2 a = __floats2half2_rn(v.x, v.y);
    __half2 b = __floats2half2_rn(v.z, v.w);
    float rx = v.x - __half2float(__low2half(a));
    float ry = v.y - __half2float(__high2half(a));
    float rz = v.z - __half2float(__low2half(b));
    float rw = v.w - __half2float(__high2half(b));
    __half2 c = __floats2half2_rn(rx, ry);
    __half2 d = __floats2half2_rn(rz, rw);
    h0 = *reinterpret_cast<uint32_t*>(&a);
    h1 = *reinterpret_cast<uint32_t*>(&b);
    l0 = *reinterpret_cast<uint32_t*>(&c);
    l1 = *reinterpret_cast<uint32_t*>(&d);
}
#define CPASYNC16(dst, src) \
    asm volatile("cp.async.cg.shared.global [%0], [%1], 16;" :: "r"(dst), "l"(src))
#define CP_COMMIT() asm volatile("cp.async.commit_group;" ::: "memory")
#define CP_WAIT0()  asm volatile("cp.async.wait_group 0;" ::: "memory")

// ---------------- pre-kernel: K -> fp16 hi/lo, V -> fp16 ----------------
__global__ void __launch_bounds__(256)
convert_kv(const float* __restrict__ k, const float* __restrict__ v) {
    const size_t i = ((size_t)blockIdx.x * 256 + threadIdx.x) * 4;
    float4 kx = *(const float4*)(k + i);
    float4 vx = *(const float4*)(v + i);
    uint32_t h0, h1, l0, l1;
    split4h(kx, h0, h1, l0, l1);
    *(uint2*)(&gKV[0][i]) = make_uint2(h0, h1);
    *(uint2*)(&gKV[1][i]) = make_uint2(l0, l1);
    *(uint2*)(&gKV[2][i]) = make_uint2(cvt2h(vx.x, vx.y), cvt2h(vx.z, vx.w));
}

// ---------------- main kernel (one split of KV per CTA) ----------------
__global__ void __launch_bounds__(NTHR, 2)
relattn_mma(const float* __restrict__ q, const float* __restrict__ bias) {
    extern __shared__ char smem[];
    const uint32_t sb = s2u(smem);
    float* bl = (float*)(smem + OFF_BL);

    const int tid  = threadIdx.x;
    const int wid  = tid >> 5;
    const int lane = tid & 31;
    const int head = blockIdx.y;
    const int spl  = blockIdx.z;
    const int q0   = blockIdx.x * BM;
    const int tile0 = spl * TPS;

    const float* qh = q + (size_t)head * LSEQ * DH;
    const size_t hb = (size_t)head * LSEQ * DH;
    float* oP = gO + (size_t)spl * NELEM + hb;
    float* rP = gRS + ((size_t)spl * NHEAD + head) * LSEQ;

    const int crow = tid >> 2;
    const int cg   = (tid & 3) * 2;
    const uint32_t cdst = sb + (uint32_t)(crow * PITCH + cg * 16);

#define ISSUE_KV(n0_, buf_) do {                                              \
        const __half* s_ = &gKV[0][hb + (size_t)((n0_) + crow) * DH + cg * 8]; \
        CPASYNC16(cdst + KHIB(buf_),      s_);                                \
        CPASYNC16(cdst + KHIB(buf_) + 16, s_ + 8);                            \
        CPASYNC16(cdst + KLOB(buf_),      s_ + NELEM);                        \
        CPASYNC16(cdst + KLOB(buf_) + 16, s_ + NELEM + 8);                    \
        CPASYNC16(cdst + VHIB(buf_),      s_ + 2 * NELEM);                    \
        CPASYNC16(cdst + VHIB(buf_) + 16, s_ + 2 * NELEM + 8);                \
        CP_COMMIT();                                                          \
    } while (0)

    ISSUE_KV(tile0 * BN, 0);

    if (tid < 2 * MAXREL + 1)
        bl[tid] = (bias[tid] - 12.0f) * LOG2E;

    // ---- persistent Q fragments (single fp16, pre-scaled 1/8) ----
    const int row0 = q0 + wid * 16 + (lane >> 2);
    const int ccol = (lane & 3) * 2;
    uint32_t qf[4][4];
#pragma unroll
    for (int s = 0; s < 4; ++s) {
        const int c = s * 16 + ccol;
        float2 x0 = *(const float2*)&qh[(size_t)row0 * DH + c];
        float2 x1 = *(const float2*)&qh[(size_t)(row0 + 8) * DH + c];
        float2 x2 = *(const float2*)&qh[(size_t)row0 * DH + c + 8];
        float2 x3 = *(const float2*)&qh[(size_t)(row0 + 8) * DH + c + 8];
        qf[s][0] = cvt2h(x0.x * 0.125f, x0.y * 0.125f);
        qf[s][1] = cvt2h(x1.x * 0.125f, x1.y * 0.125f);
        qf[s][2] = cvt2h(x2.x * 0.125f, x2.y * 0.125f);
        qf[s][3] = cvt2h(x3.x * 0.125f, x3.y * 0.125f);
    }

    const uint32_t laneK = (uint32_t)(((lane & 7) + ((lane >> 4) & 1) * 8) * PITCH
                                      + ((lane >> 3) & 1) * 16);
    const uint32_t laneV = (uint32_t)(((lane & 7) + ((lane >> 3) & 1) * 8) * PITCH
                                      + ((lane >> 4) & 1) * 16);

    float oc[8][4];
#pragma unroll
    for (int i = 0; i < 8; ++i)
#pragma unroll
        for (int j = 0; j < 4; ++j) oc[i][j] = 0.0f;
    float rs0 = 0.0f, rs1 = 0.0f;
    const int relb = ccol - row0;

    for (int tt = 0; tt < TPS; ++tt) {
        const int n0 = (tile0 + tt) * BN;
        const int buf = tt & 1;

        CP_WAIT0();
        __syncthreads();                       // tile staged; previous consumed

        if (tt + 1 < TPS) ISSUE_KV(n0 + BN, buf ^ 1);

        const int mx = n0 + BN - 1 - q0;
        const int mn = n0 - (q0 + BM - 1);
        const bool generic = (mx > -MAXREL) && (mn < MAXREL);
        const float blc = (mx <= -MAXREL) ? bl[0] : bl[2 * MAXREL];

        // ---- per 16-col chunk: S-MMA -> exp -> split-P -> PV-MMA ----
#pragma unroll
        for (int np = 0; np < 4; ++np) {
            float se[4] = {0.f, 0.f, 0.f, 0.f};
            float so[4] = {0.f, 0.f, 0.f, 0.f};
#pragma unroll
            for (int s = 0; s < 4; ++s) {
                uint32_t kH[4], kL[4];
                uint32_t a = sb + (uint32_t)(np * 16 * PITCH + s * 32) + laneK;
                ldsm4(kH, a + KHIB(buf));
                ldsm4(kL, a + KLOB(buf));
                mma16816(se, qf[s], kH);
                mma16816(so, qf[s], kH + 2);
                mma16816(se, qf[s], kL);
                mma16816(so, qf[s], kL + 2);
            }

            uint32_t pH[4], pL[4];
#pragma unroll
            for (int h = 0; h < 2; ++h) {
                float* c = h ? so : se;
                float e0, e1, e2, e3;
                if (generic) {
                    const int r0i = relb + n0 + (2 * np + h) * 8;
                    const float b0 = bl[min(max(r0i,     -MAXREL), MAXREL) + MAXREL];
                    const float b1 = bl[min(max(r0i + 1, -MAXREL), MAXREL) + MAXREL];
                    const float b2 = bl[min(max(r0i - 8, -MAXREL), MAXREL) + MAXREL];
                    const float b3 = bl[min(max(r0i - 7, -MAXREL), MAXREL) + MAXREL];
                    e0 = exp2_fast(fmaf(c[0], LOG2E, b0));
                    e1 = exp2_fast(fmaf(c[1], LOG2E, b1));
                    e2 = exp2_fast(fmaf(c[2], LOG2E, b2));
                    e3 = exp2_fast(fmaf(c[3], LOG2E, b3));
                } else {
                    e0 = exp2_fast(fmaf(c[0], LOG2E, blc));
                    e1 = exp2_fast(fmaf(c[1], LOG2E, blc));
                    e2 = exp2_fast(fmaf(c[2], LOG2E, blc));
                    e3 = exp2_fast(fmaf(c[3], LOG2E, blc));
                }
                rs0 += e0 + e1;
                rs1 += e2 + e3;
                uint32_t h01 = cvt2h(e0, e1), h23 = cvt2h(e2, e3);
                pH[2 * h]     = h01;
                pH[2 * h + 1] = h23;
                pL[2 * h]     = cvt2h(e0 - h2lo(h01), e1 - h2hi(h01));
                pL[2 * h + 1] = cvt2h(e2 - h2lo(h23), e3 - h2hi(h23));
            }

#pragma unroll
            for (int j = 0; j < 4; ++j) {
                uint32_t vH[4];
                ldsm4t(vH, sb + (uint32_t)(np * 16 * PITCH + j * 32) + laneV + VHIB(buf));
                mma16816(oc[2 * j],     pH, vH);
                mma16816(oc[2 * j + 1], pH, vH + 2);
                mma16816(oc[2 * j],     pL, vH);
                mma16816(oc[2 * j + 1], pL, vH + 2);
            }
        }
    }

    // ---- epilogue: partial rowsums + unnormalized partial O to scratch ----
    rs0 += __shfl_xor_sync(0xffffffffu, rs0, 1);
    rs0 += __shfl_xor_sync(0xffffffffu, rs0, 2);
    rs1 += __shfl_xor_sync(0xffffffffu, rs1, 1);
    rs1 += __shfl_xor_sync(0xffffffffu, rs1, 2);
    if ((lane & 3) == 0) {
        rP[row0]     = rs0;
        rP[row0 + 8] = rs1;
    }

    float* d0 = oP + (size_t)row0 * DH + ccol;
    float* d1 = d0 + 8 * DH;
#pragma unroll
    for (int nt = 0; nt < 8; ++nt) {
        *(float2*)(d0 + nt * 8) = make_float2(oc[nt][0], oc[nt][1]);
        *(float2*)(d1 + nt * 8) = make_float2(oc[nt][2], oc[nt][3]);
    }
}

// ---------------- combine kernel: out = sum(O_s) / sum(rs_s) ----------------
__global__ void __launch_bounds__(256)
combine_splits(float* __restrict__ out) {
    const size_t e = ((size_t)blockIdx.x * 256 + threadIdx.x) * 4;  // element idx
    const size_t row = e / DH;                                       // head*L + seq
    float4 acc = make_float4(0.f, 0.f, 0.f, 0.f);
    float rsum = 0.f;
#pragma unroll
    for (int s = 0; s < NSPLIT; ++s) {
        float4 t = *(const float4*)(gO + (size_t)s * NELEM + e);
        acc.x += t.x; acc.y += t.y; acc.z += t.z; acc.w += t.w;
        rsum += gRS[(size_t)s * NHEAD * LSEQ + row];
    }
    const float inv = 1.0f / rsum;
    acc.x *= inv; acc.y *= inv; acc.z *= inv; acc.w *= inv;
    *(float4*)(out + e) = acc;
}

extern "C" void kernel_launch(void* const* d_in, const int* in_sizes, int n_in,
                              void* d_out, int out_size) {
    (void)in_sizes; (void)n_in; (void)out_size;
    const float* q    = (const float*)d_in[0];
    const float* k    = (const float*)d_in[1];
    const float* v    = (const float*)d_in[2];
    const float* bias = (const float*)d_in[3];
    float* out = (float*)d_out;

    convert_kv<<<NELEM / (256 * 4), 256>>>(k, v);

    cudaFuncSetAttribute(relattn_mma, cudaFuncAttributeMaxDynamicSharedMemorySize,
                         SMEM_TOTAL);
    dim3 grid(LSEQ / BM, NHEAD, NSPLIT);   // 16 x 32 x 4 = 2048 work units
    relattn_mma<<<grid, NTHR, SMEM_TOTAL>>>(q, bias);

    combine_splits<<<NELEM / (256 * 4), 256>>>(out);
}

// round 15
// speedup vs baseline: 1.7162x; 1.1204x over previous
#include <cuda_runtime.h>
#include <cuda_fp16.h>
#include <cstdint>

// RelativeAttention B=2,H=16,L=2048,D=64 fp32.
// R14 structure (split-K=4, S = q*(kH+kL), PV = (pH+pL)*v, 32 MMAs/tile/warp)
// with exp moved to the MUFU pipe: ex2.approx.f32 replaces the FFMA polynomial.

#define LSEQ   2048
#define DH     64
#define NHEAD  32
#define BM     128
#define BN     64
#define NSPLIT 4
#define TPS    (LSEQ / BN / NSPLIT)   // 8 tiles per split
#define NTHR   256
#define MAXREL 8
#define LOG2E  1.4426950408889634f
#define NELEM  (NHEAD * LSEQ * DH)

#define PITCH  144
#define BUFHALF 27648                 // 3 arrays * 64*144
#define OFF_BL  0
#define OFF_BUF 128
#define KHIB(b) (OFF_BUF + (b) * BUFHALF + 0)
#define KLOB(b) (OFF_BUF + (b) * BUFHALF + 9216)
#define VHIB(b) (OFF_BUF + (b) * BUFHALF + 18432)
#define SMEM_TOTAL (128 + 2 * BUFHALF)   // 55424 B/CTA

__device__ __half gKV[3][NELEM];            // [0]=K_hi [1]=K_lo [2]=V
__device__ float  gO[NSPLIT * NELEM];       // unnormalized partial O
__device__ float  gRS[NSPLIT * NHEAD * LSEQ];  // partial rowsums

// ---------------- helpers ----------------
__device__ __forceinline__ uint32_t s2u(const void* p) {
    uint32_t a;
    asm("{ .reg .u64 t; cvta.to.shared.u64 t, %1; cvt.u32.u64 %0, t; }" : "=r"(a) : "l"(p));
    return a;
}
__device__ __forceinline__ uint32_t cvt2h(float lo, float hi) {
    __half2 t = __floats2half2_rn(lo, hi);
    return *reinterpret_cast<uint32_t*>(&t);
}
__device__ __forceinline__ float h2lo(uint32_t p) {
    __half2 t = *reinterpret_cast<__half2*>(&p);
    return __half2float(__low2half(t));
}
__device__ __forceinline__ float h2hi(uint32_t p) {
    __half2 t = *reinterpret_cast<__half2*>(&p);
    return __half2float(__high2half(t));
}
__device__ __forceinline__ float ex2f(float x) {         // MUFU pipe
    float y;
    asm("ex2.approx.f32 %0, %1;" : "=f"(y) : "f"(x));
    return y;
}
__device__ __forceinline__ void mma16816(float* c, const uint32_t* a, const uint32_t* b) {
    asm volatile(
        "mma.sync.aligned.m16n8k16.row.col.f32.f16.f16.f32 "
        "{%0,%1,%2,%3}, {%4,%5,%6,%7}, {%8,%9}, {%0,%1,%2,%3};"
        : "+f"(c[0]), "+f"(c[1]), "+f"(c[2]), "+f"(c[3])
        : "r"(a[0]), "r"(a[1]), "r"(a[2]), "r"(a[3]), "r"(b[0]), "r"(b[1]));
}
__device__ __forceinline__ void ldsm4(uint32_t* r, uint32_t addr) {
    asm volatile("ldmatrix.sync.aligned.m8n8.x4.shared.b16 {%0,%1,%2,%3}, [%4];"
                 : "=r"(r[0]), "=r"(r[1]), "=r"(r[2]), "=r"(r[3]) : "r"(addr));
}
__device__ __forceinline__ void ldsm4t(uint32_t* r, uint32_t addr) {
    asm volatile("ldmatrix.sync.aligned.m8n8.x4.trans.shared.b16 {%0,%1,%2,%3}, [%4];"
                 : "=r"(r[0]), "=r"(r[1]), "=r"(r[2]), "=r"(r[3]) : "r"(addr));
}
__device__ __forceinline__ void split4h(float4 v, uint32_t& h0, uint32_t& h1,
                                        uint32_t& l0, uint32_t& l1) {
    __half2 a = __floats2half2_rn(v.x, v.y);
    __half2 b = __floats2half2_rn(v.z, v.w);
    float rx = v.x - __half2float(__low2half(a));
    float ry = v.y - __half2float(__high2half(a));
    float rz = v.z - __half2float(__low2half(b));
    float rw = v.w - __half2float(__high2half(b));
    __half2 c = __floats2half2_rn(rx, ry);
    __half2 d = __floats2half2_rn(rz, rw);
    h0 = *reinterpret_cast<uint32_t*>(&a);
    h1 = *reinterpret_cast<uint32_t*>(&b);
    l0 = *reinterpret_cast<uint32_t*>(&c);
    l1 = *reinterpret_cast<uint32_t*>(&d);
}
#define CPASYNC16(dst, src) \
    asm volatile("cp.async.cg.shared.global [%0], [%1], 16;" :: "r"(dst), "l"(src))
#define CP_COMMIT() asm volatile("cp.async.commit_group;" ::: "memory")
#define CP_WAIT0()  asm volatile("cp.async.wait_group 0;" ::: "memory")

// ---------------- pre-kernel: K -> fp16 hi/lo, V -> fp16 ----------------
__global__ void __launch_bounds__(256)
convert_kv(const float* __restrict__ k, const float* __restrict__ v) {
    const size_t i = ((size_t)blockIdx.x * 256 + threadIdx.x) * 4;
    float4 kx = *(const float4*)(k + i);
    float4 vx = *(const float4*)(v + i);
    uint32_t h0, h1, l0, l1;
    split4h(kx, h0, h1, l0, l1);
    *(uint2*)(&gKV[0][i]) = make_uint2(h0, h1);
    *(uint2*)(&gKV[1][i]) = make_uint2(l0, l1);
    *(uint2*)(&gKV[2][i]) = make_uint2(cvt2h(vx.x, vx.y), cvt2h(vx.z, vx.w));
}

// ---------------- main kernel (one split of KV per CTA) ----------------
__global__ void __launch_bounds__(NTHR, 2)
relattn_mma(const float* __restrict__ q, const float* __restrict__ bias) {
    extern __shared__ char smem[];
    const uint32_t sb = s2u(smem);
    float* bl = (float*)(smem + OFF_BL);

    const int tid  = threadIdx.x;
    const int wid  = tid >> 5;
    const int lane = tid & 31;
    const int head = blockIdx.y;
    const int spl  = blockIdx.z;
    const int q0   = blockIdx.x * BM;
    const int tile0 = spl * TPS;

    const float* qh = q + (size_t)head * LSEQ * DH;
    const size_t hb = (size_t)head * LSEQ * DH;
    float* oP = gO + (size_t)spl * NELEM + hb;
    float* rP = gRS + ((size_t)spl * NHEAD + head) * LSEQ;

    const int crow = tid >> 2;
    const int cg   = (tid & 3) * 2;
    const uint32_t cdst = sb + (uint32_t)(crow * PITCH + cg * 16);

#define ISSUE_KV(n0_, buf_) do {                                              \
        const __half* s_ = &gKV[0][hb + (size_t)((n0_) + crow) * DH + cg * 8]; \
        CPASYNC16(cdst + KHIB(buf_),      s_);                                \
        CPASYNC16(cdst + KHIB(buf_) + 16, s_ + 8);                            \
        CPASYNC16(cdst + KLOB(buf_),      s_ + NELEM);                        \
        CPASYNC16(cdst + KLOB(buf_) + 16, s_ + NELEM + 8);                    \
        CPASYNC16(cdst + VHIB(buf_),      s_ + 2 * NELEM);                    \
        CPASYNC16(cdst + VHIB(buf_) + 16, s_ + 2 * NELEM + 8);                \
        CP_COMMIT();                                                          \
    } while (0)

    ISSUE_KV(tile0 * BN, 0);

    if (tid < 2 * MAXREL + 1)
        bl[tid] = (bias[tid] - 12.0f) * LOG2E;

    // ---- persistent Q fragments (single fp16, pre-scaled 1/8) ----
    const int row0 = q0 + wid * 16 + (lane >> 2);
    const int ccol = (lane & 3) * 2;
    uint32_t qf[4][4];
#pragma unroll
    for (int s = 0; s < 4; ++s) {
        const int c = s * 16 + ccol;
        float2 x0 = *(const float2*)&qh[(size_t)row0 * DH + c];
        float2 x1 = *(const float2*)&qh[(size_t)(row0 + 8) * DH + c];
        float2 x2 = *(const float2*)&qh[(size_t)row0 * DH + c + 8];
        float2 x3 = *(const float2*)&qh[(size_t)(row0 + 8) * DH + c + 8];
        qf[s][0] = cvt2h(x0.x * 0.125f, x0.y * 0.125f);
        qf[s][1] = cvt2h(x1.x * 0.125f, x1.y * 0.125f);
        qf[s][2] = cvt2h(x2.x * 0.125f, x2.y * 0.125f);
        qf[s][3] = cvt2h(x3.x * 0.125f, x3.y * 0.125f);
    }

    const uint32_t laneK = (uint32_t)(((lane & 7) + ((lane >> 4) & 1) * 8) * PITCH
                                      + ((lane >> 3) & 1) * 16);
    const uint32_t laneV = (uint32_t)(((lane & 7) + ((lane >> 3) & 1) * 8) * PITCH
                                      + ((lane >> 4) & 1) * 16);

    float oc[8][4];
#pragma unroll
    for (int i = 0; i < 8; ++i)
#pragma unroll
        for (int j = 0; j < 4; ++j) oc[i][j] = 0.0f;
    float rs0 = 0.0f, rs1 = 0.0f;
    const int relb = ccol - row0;

    for (int tt = 0; tt < TPS; ++tt) {
        const int n0 = (tile0 + tt) * BN;
        const int buf = tt & 1;

        CP_WAIT0();
        __syncthreads();                       // tile staged; previous consumed

        if (tt + 1 < TPS) ISSUE_KV(n0 + BN, buf ^ 1);

        const int mx = n0 + BN - 1 - q0;
        const int mn = n0 - (q0 + BM - 1);
        const bool generic = (mx > -MAXREL) && (mn < MAXREL);
        const float blc = (mx <= -MAXREL) ? bl[0] : bl[2 * MAXREL];

        // ---- per 16-col chunk: S-MMA -> exp(MUFU) -> split-P -> PV-MMA ----
#pragma unroll
        for (int np = 0; np < 4; ++np) {
            float se[4] = {0.f, 0.f, 0.f, 0.f};
            float so[4] = {0.f, 0.f, 0.f, 0.f};
#pragma unroll
            for (int s = 0; s < 4; ++s) {
                uint32_t kH[4], kL[4];
                uint32_t a = sb + (uint32_t)(np * 16 * PITCH + s * 32) + laneK;
                ldsm4(kH, a + KHIB(buf));
                ldsm4(kL, a + KLOB(buf));
                mma16816(se, qf[s], kH);
                mma16816(so, qf[s], kH + 2);
                mma16816(se, qf[s], kL);
                mma16816(so, qf[s], kL + 2);
            }

            uint32_t pH[4], pL[4];
#pragma unroll
            for (int h = 0; h < 2; ++h) {
                float* c = h ? so : se;
                float e0, e1, e2, e3;
                if (generic) {
                    const int r0i = relb + n0 + (2 * np + h) * 8;
                    const float b0 = bl[min(max(r0i,     -MAXREL), MAXREL) + MAXREL];
                    const float b1 = bl[min(max(r0i + 1, -MAXREL), MAXREL) + MAXREL];
                    const float b2 = bl[min(max(r0i - 8, -MAXREL), MAXREL) + MAXREL];
                    const float b3 = bl[min(max(r0i - 7, -MAXREL), MAXREL) + MAXREL];
                    e0 = ex2f(fmaf(c[0], LOG2E, b0));
                    e1 = ex2f(fmaf(c[1], LOG2E, b1));
                    e2 = ex2f(fmaf(c[2], LOG2E, b2));
                    e3 = ex2f(fmaf(c[3], LOG2E, b3));
                } else {
                    e0 = ex2f(fmaf(c[0], LOG2E, blc));
                    e1 = ex2f(fmaf(c[1], LOG2E, blc));
                    e2 = ex2f(fmaf(c[2], LOG2E, blc));
                    e3 = ex2f(fmaf(c[3], LOG2E, blc));
                }
                rs0 += e0 + e1;
                rs1 += e2 + e3;
                uint32_t h01 = cvt2h(e0, e1), h23 = cvt2h(e2, e3);
                pH[2 * h]     = h01;
                pH[2 * h + 1] = h23;
                pL[2 * h]     = cvt2h(e0 - h2lo(h01), e1 - h2hi(h01));
                pL[2 * h + 1] = cvt2h(e2 - h2lo(h23), e3 - h2hi(h23));
            }

#pragma unroll
            for (int j = 0; j < 4; ++j) {
                uint32_t vH[4];
                ldsm4t(vH, sb + (uint32_t)(np * 16 * PITCH + j * 32) + laneV + VHIB(buf));
                mma16816(oc[2 * j],     pH, vH);
                mma16816(oc[2 * j + 1], pH, vH + 2);
                mma16816(oc[2 * j],     pL, vH);
                mma16816(oc[2 * j + 1], pL, vH + 2);
            }
        }
    }

    // ---- epilogue: partial rowsums + unnormalized partial O to scratch ----
    rs0 += __shfl_xor_sync(0xffffffffu, rs0, 1);
    rs0 += __shfl_xor_sync(0xffffffffu, rs0, 2);
    rs1 += __shfl_xor_sync(0xffffffffu, rs1, 1);
    rs1 += __shfl_xor_sync(0xffffffffu, rs1, 2);
    if ((lane & 3) == 0) {
        rP[row0]     = rs0;
        rP[row0 + 8] = rs1;
    }

    float* d0 = oP + (size_t)row0 * DH + ccol;
    float* d1 = d0 + 8 * DH;
#pragma unroll
    for (int nt = 0; nt < 8; ++nt) {
        *(float2*)(d0 + nt * 8) = make_float2(oc[nt][0], oc[nt][1]);
        *(float2*)(d1 + nt * 8) = make_float2(oc[nt][2], oc[nt][3]);
    }
}

// ---------------- combine kernel: out = sum(O_s) / sum(rs_s) ----------------
__global__ void __launch_bounds__(256)
combine_splits(float* __restrict__ out) {
    const size_t e = ((size_t)blockIdx.x * 256 + threadIdx.x) * 4;
    const size_t row = e / DH;
    float4 acc = make_float4(0.f, 0.f, 0.f, 0.f);
    float rsum = 0.f;
#pragma unroll
    for (int s = 0; s < NSPLIT; ++s) {
        float4 t = *(const float4*)(gO + (size_t)s * NELEM + e);
        acc.x += t.x; acc.y += t.y; acc.z += t.z; acc.w += t.w;
        rsum += gRS[(size_t)s * NHEAD * LSEQ + row];
    }
    const float inv = 1.0f / rsum;
    acc.x *= inv; acc.y *= inv; acc.z *= inv; acc.w *= inv;
    *(float4*)(out + e) = acc;
}

extern "C" void kernel_launch(void* const* d_in, const int* in_sizes, int n_in,
                              void* d_out, int out_size) {
    (void)in_sizes; (void)n_in; (void)out_size;
    const float* q    = (const float*)d_in[0];
    const float* k    = (const float*)d_in[1];
    const float* v    = (const float*)d_in[2];
    const float* bias = (const float*)d_in[3];
    float* out = (float*)d_out;

    convert_kv<<<NELEM / (256 * 4), 256>>>(k, v);

    cudaFuncSetAttribute(relattn_mma, cudaFuncAttributeMaxDynamicSharedMemorySize,
                         SMEM_TOTAL);
    dim3 grid(LSEQ / BM, NHEAD, NSPLIT);   // 2048 work units
    relattn_mma<<<grid, NTHR, SMEM_TOTAL>>>(q, bias);

    combine_splits<<<NELEM / (256 * 4), 256>>>(out);
}